// round 9
// baseline (speedup 1.0000x reference)
#include <cuda_runtime.h>
#include <cuda_bf16.h>
#include <stdint.h>

// ============================================================================
// BFP8 quantized 3x3 conv (stride 1, pad 1) == GEMM M=100352, N=256, K=1152
// Round 9: int8 IMMA path + packed f32x2 flush (sm_100 fma.rn.f32x2).
//   K1: quantize weight -> s8 + scales (warp per 64-block)
//   K2: quantize im2col(A) -> s8 (110MB) + scales
//   K3: s8 GEMM 128x128 tile, 256 thr, 2-stage cp.async, 2 CTAs/SM,
//       per-block scale flush via packed f32x2 FFMA (half the fp-pipe slots).
// ============================================================================

#define C_IN      128
#define C_OUT     256
#define HWDIM     56
#define IMG_PIX   3136
#define K_TOTAL   1152
#define M_TOTAL   100352
#define GRID_M    784
#define NBLK      18

typedef unsigned long long ull;

__device__ __align__(16) int8_t g_wq8[C_OUT * K_TOTAL];
__device__ float   g_sw[NBLK * C_OUT];                    // [b][n]
__device__ __align__(16) int8_t g_qa8[(size_t)M_TOTAL * K_TOTAL];   // 110 MB
__device__ float   g_sa[(size_t)NBLK * M_TOTAL];          // [b][m]

// ---------------------------------------------------------------------------
__device__ __forceinline__ uint32_t cvta_smem(const void* p) {
    uint32_t a;
    asm("{ .reg .u64 t; cvta.to.shared.u64 t, %1; cvt.u32.u64 %0, t; }"
        : "=r"(a) : "l"(p));
    return a;
}
__device__ __forceinline__ void ldsm_x4(uint32_t* d, uint32_t addr) {
    asm volatile("ldmatrix.sync.aligned.m8n8.x4.shared.b16 {%0,%1,%2,%3}, [%4];"
                 : "=r"(d[0]), "=r"(d[1]), "=r"(d[2]), "=r"(d[3]) : "r"(addr));
}
__device__ __forceinline__ void imma_init(int* d, const uint32_t* a,
                                          uint32_t b0, uint32_t b1) {
    asm volatile(
        "mma.sync.aligned.m16n8k32.row.col.s32.s8.s8.s32 "
        "{%0,%1,%2,%3}, {%4,%5,%6,%7}, {%8,%9}, {%10,%10,%10,%10};"
        : "=r"(d[0]), "=r"(d[1]), "=r"(d[2]), "=r"(d[3])
        : "r"(a[0]), "r"(a[1]), "r"(a[2]), "r"(a[3]),
          "r"(b0), "r"(b1), "r"(0));
}
__device__ __forceinline__ void imma_acc(int* d, const uint32_t* a,
                                         uint32_t b0, uint32_t b1) {
    asm volatile(
        "mma.sync.aligned.m16n8k32.row.col.s32.s8.s8.s32 "
        "{%0,%1,%2,%3}, {%4,%5,%6,%7}, {%8,%9}, {%0,%1,%2,%3};"
        : "+r"(d[0]), "+r"(d[1]), "+r"(d[2]), "+r"(d[3])
        : "r"(a[0]), "r"(a[1]), "r"(a[2]), "r"(a[3]), "r"(b0), "r"(b1));
}
__device__ __forceinline__ void cp_async16(uint32_t dst, const void* src) {
    asm volatile("cp.async.cg.shared.global [%0], [%1], 16;" :: "r"(dst), "l"(src));
}
__device__ __forceinline__ void cp_commit() {
    asm volatile("cp.async.commit_group;");
}
template <int N>
__device__ __forceinline__ void cp_wait() {
    asm volatile("cp.async.wait_group %0;" :: "n"(N));
}

// ---- packed f32x2 helpers (sm_100 PTX) ----
__device__ __forceinline__ ull pk2(float lo, float hi) {
    ull r;
    asm("mov.b64 %0, {%1, %2};" : "=l"(r) : "f"(lo), "f"(hi));
    return r;
}
__device__ __forceinline__ ull mul2(ull a, ull b) {
    ull r;
    asm("mul.rn.f32x2 %0, %1, %2;" : "=l"(r) : "l"(a), "l"(b));
    return r;
}
__device__ __forceinline__ void fma2(ull& d, ull a, ull b) {
    asm("fma.rn.f32x2 %0, %1, %2, %0;" : "+l"(d) : "l"(a), "l"(b));
}
__device__ __forceinline__ void unpk2(float& lo, float& hi, ull v) {
    asm("mov.b64 {%0, %1}, %2;" : "=f"(lo), "=f"(hi) : "l"(v));
}

__device__ __forceinline__ int block_exp(float mx) {
    mx = fmaxf(mx, 1e-38f);
    return ((__float_as_int(mx) >> 23) & 255) - 127;
}
__device__ __forceinline__ int qint(float x, float inv) {
    float q = rintf(x * inv);
    q = fminf(q, 127.0f);
    return (int)q;
}
__device__ __forceinline__ uint32_t pack4(int i0, int i1, int i2, int i3) {
    return (uint32_t)(i0 & 0xff) | ((uint32_t)(i1 & 0xff) << 8)
         | ((uint32_t)(i2 & 0xff) << 16) | ((uint32_t)i3 << 24);
}

// ---------------------------------------------------------------------------
// Kernel 1: quantize weight. One warp per (row, 64-block). grid (18, 256).
// ---------------------------------------------------------------------------
__global__ void quant_w8_kernel(const float* __restrict__ w) {
    const int b    = blockIdx.x;
    const int row  = blockIdx.y;
    const int lane = threadIdx.x;
    const float* src = w + (size_t)row * K_TOTAL + b * 64;

    float a0 = __ldg(src + lane);
    float a1 = __ldg(src + 32 + lane);
    float mx = fmaxf(fabsf(a0), fabsf(a1));
#pragma unroll
    for (int o = 16; o > 0; o >>= 1)
        mx = fmaxf(mx, __shfl_xor_sync(0xFFFFFFFFu, mx, o));
    int e = block_exp(mx);
    float scale = __int_as_float((e + 121) << 23);
    float inv   = __int_as_float((133 - e) << 23);
    int8_t* dst = g_wq8 + (size_t)row * K_TOTAL + b * 64;
    dst[lane]      = (int8_t)qint(a0, inv);
    dst[32 + lane] = (int8_t)qint(a1, inv);
    if (lane == 0) g_sw[b * C_OUT + row] = scale;
}

// ---------------------------------------------------------------------------
// Kernel 2: quantize im2col(A). grid (784, 18), 256 threads.
// ---------------------------------------------------------------------------
template <int S>
__device__ __forceinline__ void gather32(const float* __restrict__ pix,
                                         uint32_t vmask, float* v, float& mx) {
#pragma unroll
    for (int e = 0; e < 32; ++e) {
        const int u   = S + e;
        const int ci  = u / 9;
        const int tap = u % 9;
        const int off = ci * IMG_PIX + (tap / 3) * HWDIM + (tap % 3);
        float val = ((vmask >> tap) & 1u) ? __ldg(pix + off) : 0.0f;
        v[e] = val;
        mx = fmaxf(mx, fabsf(val));
    }
}

__global__ void quant_a8_kernel(const float* __restrict__ inp) {
    __shared__ float smax[256];
    const int tid  = threadIdx.x;
    const int r    = tid & 127;
    const int half = tid >> 7;
    const int m  = blockIdx.x * 128 + r;
    const int b  = blockIdx.y;
    const int t0 = b % 9;
    const int c0 = (64 * b) / 9;

    const int ni = m / IMG_PIX;
    const int p  = m - ni * IMG_PIX;
    const int ho = p / HWDIM;
    const int wo = p - ho * HWDIM;
    const float* pix = inp + ((size_t)ni * C_IN + c0) * IMG_PIX
                       + ho * HWDIM + wo - 57;

    uint32_t vmask = 0;
#pragma unroll
    for (int kh = 0; kh < 3; ++kh)
#pragma unroll
        for (int kw = 0; kw < 3; ++kw) {
            int h = ho + kh - 1, w = wo + kw - 1;
            if ((unsigned)h < (unsigned)HWDIM && (unsigned)w < (unsigned)HWDIM)
                vmask |= 1u << (kh * 3 + kw);
        }

    float v[32];
    float mx = 0.0f;
    switch (t0) {
        case 0: if (half) gather32<32>(pix, vmask, v, mx); else gather32<0>(pix, vmask, v, mx); break;
        case 1: if (half) gather32<33>(pix, vmask, v, mx); else gather32<1>(pix, vmask, v, mx); break;
        case 2: if (half) gather32<34>(pix, vmask, v, mx); else gather32<2>(pix, vmask, v, mx); break;
        case 3: if (half) gather32<35>(pix, vmask, v, mx); else gather32<3>(pix, vmask, v, mx); break;
        case 4: if (half) gather32<36>(pix, vmask, v, mx); else gather32<4>(pix, vmask, v, mx); break;
        case 5: if (half) gather32<37>(pix, vmask, v, mx); else gather32<5>(pix, vmask, v, mx); break;
        case 6: if (half) gather32<38>(pix, vmask, v, mx); else gather32<6>(pix, vmask, v, mx); break;
        case 7: if (half) gather32<39>(pix, vmask, v, mx); else gather32<7>(pix, vmask, v, mx); break;
        default:if (half) gather32<40>(pix, vmask, v, mx); else gather32<8>(pix, vmask, v, mx); break;
    }

    smax[tid] = mx;
    __syncthreads();
    mx = fmaxf(mx, smax[tid ^ 128]);

    int e = block_exp(mx);
    float scale = __int_as_float((e + 121) << 23);
    float inv   = __int_as_float((133 - e) << 23);

    uint32_t pk[8];
#pragma unroll
    for (int i = 0; i < 8; ++i)
        pk[i] = pack4(qint(v[4*i], inv),   qint(v[4*i+1], inv),
                      qint(v[4*i+2], inv), qint(v[4*i+3], inv));
    uint4* dst = reinterpret_cast<uint4*>(g_qa8 + (size_t)m * K_TOTAL
                                          + b * 64 + half * 32);
    dst[0] = make_uint4(pk[0], pk[1], pk[2], pk[3]);
    dst[1] = make_uint4(pk[4], pk[5], pk[6], pk[7]);
    if (half == 0) g_sa[(size_t)b * M_TOTAL + m] = scale;
}

// ---------------------------------------------------------------------------
// Kernel 3: s8 GEMM. Tile 128x128, 256 threads (8 warps 4x2), warp 32x64.
// CHUNK_K=128 (2 BFP blocks) per stage; 9 iters; 2-stage cp.async; 2 CTAs/SM.
// Flush uses packed f32x2 FMA.
// ---------------------------------------------------------------------------
#define A_SZ      16384
#define B_SZ      16384
#define STAGE     (A_SZ + B_SZ)         // 32768
#define SCALE_OFF (2 * STAGE)           // 65536
#define SA_WORDS  (NBLK * 128)          // 2304
#define SW_WORDS  (NBLK * 128)          // 2304
#define K3_SMEM   (SCALE_OFF + 4 * (SA_WORDS + SW_WORDS))   // 83968
#define C_STRIDE  132

__global__ __launch_bounds__(256, 2)
void gemm8_kernel(const float* __restrict__ bias, float* __restrict__ out) {
    extern __shared__ __align__(16) char smem[];
    const uint32_t smem_u = cvta_smem(smem);
    float* sSA = reinterpret_cast<float*>(smem + SCALE_OFF);
    float* sSW = sSA + SA_WORDS;
    const ull* sSW2 = reinterpret_cast<const ull*>(sSW);

    const int tid  = threadIdx.x;
    const int wid  = tid >> 5;
    const int lane = tid & 31;
    const int warp_m = wid & 3;
    const int warp_n = wid >> 2;
    const int ntile  = blockIdx.x;           // 0..1
    const int m_base = blockIdx.y * 128;

    // ---- preload scales ----
    for (int i = tid; i < SA_WORDS; i += 256)
        sSA[i] = g_sa[(size_t)(i >> 7) * M_TOTAL + m_base + (i & 127)];
    for (int i = tid; i < SW_WORDS; i += 256)
        sSW[i] = g_sw[(i >> 7) * C_OUT + ntile * 128 + (i & 127)];

    // ---- cp.async identities ----
    const int lr = tid >> 1;
    const int jh = (tid & 1) * 4;
    const uint32_t lkey = (uint32_t)(lr & 7);
    const int8_t* a_src = g_qa8 + (size_t)(m_base + lr) * K_TOTAL;
    const int8_t* b_src = g_wq8 + (size_t)(ntile * 128 + lr) * K_TOTAL;

    auto load_stage = [&](int kc, int s) {
        const uint32_t st = smem_u + s * STAGE;
        const int ko = kc * 128;
#pragma unroll
        for (int i = 0; i < 4; ++i) {
            uint32_t u = (uint32_t)(jh + i);
            uint32_t sw = ((u ^ lkey) << 4) + (uint32_t)(lr * 128);
            cp_async16(st + sw, a_src + ko + u * 16);
            cp_async16(st + A_SZ + sw, b_src + ko + u * 16);
        }
        cp_commit();
    };

    // ---- ldsm identities ----
    const uint32_t keyA = (uint32_t)(lane & 7);
    const uint32_t hiA  = (uint32_t)(lane >> 4);
    const uint32_t baseA = (uint32_t)((warp_m * 32 + (lane & 7)
                                       + ((lane >> 3) & 1) * 8) * 128);
    const uint32_t hiB  = (uint32_t)((lane >> 3) & 1);
    const uint32_t baseB = (uint32_t)(A_SZ + (warp_n * 64 + (lane & 7)
                                              + (lane >> 4) * 8) * 128);
    const int rs0 = warp_m * 32 + (lane >> 2);
    // sSW2 packed-pair index base: (gb*128 + warp_n*64 + 2*(lane&3)) / 2
    const int swbase = warp_n * 32 + (lane & 3);

    // packed accumulators: acc2[frag][0]=(elem0,elem1), [1]=(elem2,elem3)
    ull acc2[16][2];
#pragma unroll
    for (int i = 0; i < 16; ++i) { acc2[i][0] = 0ULL; acc2[i][1] = 0ULL; }

    load_stage(0, 0);

    for (int kc = 0; kc < 9; ++kc) {
        if (kc + 1 < 9) load_stage(kc + 1, (kc + 1) & 1);
        if (kc + 1 < 9) cp_wait<1>(); else cp_wait<0>();
        __syncthreads();
        const uint32_t sb = smem_u + (kc & 1) * STAGE;

#pragma unroll
        for (int blk = 0; blk < 2; ++blk) {
            const int gb = kc * 2 + blk;
            // A-row scale broadcast pairs (ra,ra) / (rb,rb) per mt
            const float sa0 = sSA[gb * 128 + rs0];
            const float sa1 = sSA[gb * 128 + rs0 + 8];
            const float sa2 = sSA[gb * 128 + rs0 + 16];
            const float sa3 = sSA[gb * 128 + rs0 + 24];
            const ull rap[2] = { pk2(sa0, sa0), pk2(sa2, sa2) };
            const ull rbp[2] = { pk2(sa1, sa1), pk2(sa3, sa3) };

            uint32_t a[2][2][4];
#pragma unroll
            for (int mt = 0; mt < 2; ++mt)
#pragma unroll
                for (int ks = 0; ks < 2; ++ks)
                    ldsm_x4(a[mt][ks], sb + baseA + mt * 2048
                            + ((((uint32_t)(blk * 4 + ks * 2) + hiA) ^ keyA) << 4));

#pragma unroll
            for (int ntp = 0; ntp < 4; ++ntp) {
                uint32_t b0[4], b1[4];
                ldsm_x4(b0, sb + baseB + ntp * 2048
                        + ((((uint32_t)(blk * 4) + hiB) ^ keyA) << 4));
                ldsm_x4(b1, sb + baseB + ntp * 2048
                        + ((((uint32_t)(blk * 4 + 2) + hiB) ^ keyA) << 4));
                // packed weight-scale pairs (ca,cb) for nf=0,1
                const ull cp0 = sSW2[gb * 64 + swbase + ntp * 8];
                const ull cp1 = sSW2[gb * 64 + swbase + ntp * 8 + 4];
#pragma unroll
                for (int mt = 0; mt < 2; ++mt) {
#pragma unroll
                    for (int nf = 0; nf < 2; ++nf) {
                        int t[4];
                        imma_init(t, a[mt][0], b0[nf * 2], b0[nf * 2 + 1]);
                        imma_acc (t, a[mt][1], b1[nf * 2], b1[nf * 2 + 1]);
                        const ull cp = nf ? cp1 : cp0;
                        const ull tp01 = pk2(__int2float_rn(t[0]),
                                             __int2float_rn(t[1]));
                        const ull tp23 = pk2(__int2float_rn(t[2]),
                                             __int2float_rn(t[3]));
                        const int f = mt * 8 + ntp * 2 + nf;
                        fma2(acc2[f][0], mul2(rap[mt], cp), tp01);
                        fma2(acc2[f][1], mul2(rbp[mt], cp), tp23);
                    }
                }
            }
        }
        __syncthreads();
    }

    // ---- epilogue: transpose via SMEM, coalesced NCHW stores + bias ----
    float* sC = reinterpret_cast<float*>(smem);
#pragma unroll
    for (int mt = 0; mt < 2; ++mt)
#pragma unroll
        for (int nt = 0; nt < 8; ++nt) {
            int rr = warp_m * 32 + mt * 16 + (lane >> 2);
            int cc = warp_n * 64 + nt * 8 + 2 * (lane & 3);
            float f0, f1, f2, f3;
            unpk2(f0, f1, acc2[mt * 8 + nt][0]);
            unpk2(f2, f3, acc2[mt * 8 + nt][1]);
            sC[cc * C_STRIDE + rr]           = f0;
            sC[(cc + 1) * C_STRIDE + rr]     = f1;
            sC[cc * C_STRIDE + rr + 8]       = f2;
            sC[(cc + 1) * C_STRIDE + rr + 8] = f3;
        }
    __syncthreads();

#pragma unroll
    for (int j = 0; j < 4; ++j) {
        int rr = j * 32 + lane;
        int mm = m_base + rr;
        int ni2 = mm / IMG_PIX;
        int pp  = mm - ni2 * IMG_PIX;
        float* ob = out + (size_t)ni2 * (C_OUT * IMG_PIX) + pp;
#pragma unroll 4
        for (int i = 0; i < 16; ++i) {
            int cl = wid * 16 + i;
            int co = ntile * 128 + cl;
            ob[(size_t)co * IMG_PIX] = sC[cl * C_STRIDE + rr] + __ldg(bias + co);
        }
    }
}

// ---------------------------------------------------------------------------
extern "C" void kernel_launch(void* const* d_in, const int* in_sizes, int n_in,
                              void* d_out, int out_size) {
    (void)in_sizes; (void)n_in; (void)out_size;
    const float* inp  = (const float*)d_in[0];
    const float* w    = (const float*)d_in[1];
    const float* bias = (const float*)d_in[2];
    float* out = (float*)d_out;

    cudaFuncSetAttribute(gemm8_kernel,
                         cudaFuncAttributeMaxDynamicSharedMemorySize, K3_SMEM);

    quant_w8_kernel<<<dim3(NBLK, C_OUT, 1), 32>>>(w);
    quant_a8_kernel<<<dim3(GRID_M, NBLK, 1), 256>>>(inp);
    gemm8_kernel<<<dim3(2, GRID_M, 1), 256, K3_SMEM>>>(bias, out);
}

// round 10
// speedup vs baseline: 1.0420x; 1.0420x over previous
#include <cuda_runtime.h>
#include <cuda_bf16.h>
#include <stdint.h>

// ============================================================================
// BFP8 quantized 3x3 conv (stride 1, pad 1) == GEMM M=100352, N=256, K=1152
// Round 10: int8 IMMA path.
//   K1: quantize weight -> s8 + scales (warp per 64-block)
//   K2: quantize im2col(A) -> s8 + scales (one full block per thread, no syncs)
//   K3: s8 GEMM 128x128 tile, 256 thr, 3-stage cp.async ring with ONE
//       __syncthreads per chunk, u8-exponent scales in SMEM, 2 CTAs/SM.
// ============================================================================

#define C_IN      128
#define C_OUT     256
#define HWDIM     56
#define IMG_PIX   3136
#define K_TOTAL   1152
#define M_TOTAL   100352
#define GRID_M    784
#define NBLK      18

__device__ __align__(16) int8_t g_wq8[C_OUT * K_TOTAL];
__device__ float   g_sw[NBLK * C_OUT];                    // [b][n]
__device__ __align__(16) int8_t g_qa8[(size_t)M_TOTAL * K_TOTAL];   // 110 MB
__device__ float   g_sa[(size_t)NBLK * M_TOTAL];          // [b][m]

// ---------------------------------------------------------------------------
__device__ __forceinline__ uint32_t cvta_smem(const void* p) {
    uint32_t a;
    asm("{ .reg .u64 t; cvta.to.shared.u64 t, %1; cvt.u32.u64 %0, t; }"
        : "=r"(a) : "l"(p));
    return a;
}
__device__ __forceinline__ void ldsm_x4(uint32_t* d, uint32_t addr) {
    asm volatile("ldmatrix.sync.aligned.m8n8.x4.shared.b16 {%0,%1,%2,%3}, [%4];"
                 : "=r"(d[0]), "=r"(d[1]), "=r"(d[2]), "=r"(d[3]) : "r"(addr));
}
__device__ __forceinline__ void imma_init(int* d, const uint32_t* a,
                                          uint32_t b0, uint32_t b1) {
    asm volatile(
        "mma.sync.aligned.m16n8k32.row.col.s32.s8.s8.s32 "
        "{%0,%1,%2,%3}, {%4,%5,%6,%7}, {%8,%9}, {%10,%10,%10,%10};"
        : "=r"(d[0]), "=r"(d[1]), "=r"(d[2]), "=r"(d[3])
        : "r"(a[0]), "r"(a[1]), "r"(a[2]), "r"(a[3]),
          "r"(b0), "r"(b1), "r"(0));
}
__device__ __forceinline__ void imma_acc(int* d, const uint32_t* a,
                                         uint32_t b0, uint32_t b1) {
    asm volatile(
        "mma.sync.aligned.m16n8k32.row.col.s32.s8.s8.s32 "
        "{%0,%1,%2,%3}, {%4,%5,%6,%7}, {%8,%9}, {%0,%1,%2,%3};"
        : "+r"(d[0]), "+r"(d[1]), "+r"(d[2]), "+r"(d[3])
        : "r"(a[0]), "r"(a[1]), "r"(a[2]), "r"(a[3]), "r"(b0), "r"(b1));
}
__device__ __forceinline__ void cp_async16(uint32_t dst, const void* src) {
    asm volatile("cp.async.cg.shared.global [%0], [%1], 16;" :: "r"(dst), "l"(src));
}
__device__ __forceinline__ void cp_commit() {
    asm volatile("cp.async.commit_group;");
}
template <int N>
__device__ __forceinline__ void cp_wait() {
    asm volatile("cp.async.wait_group %0;" :: "n"(N));
}

__device__ __forceinline__ int block_exp(float mx) {
    mx = fmaxf(mx, 1e-38f);
    return ((__float_as_int(mx) >> 23) & 255) - 127;
}
__device__ __forceinline__ int qint(float x, float inv) {
    float q = rintf(x * inv);
    q = fminf(q, 127.0f);
    return (int)q;
}
__device__ __forceinline__ uint32_t pack4(int i0, int i1, int i2, int i3) {
    return (uint32_t)(i0 & 0xff) | ((uint32_t)(i1 & 0xff) << 8)
         | ((uint32_t)(i2 & 0xff) << 16) | ((uint32_t)i3 << 24);
}

// ---------------------------------------------------------------------------
// Kernel 1: quantize weight. One warp per (row, 64-block). grid (18, 256).
// ---------------------------------------------------------------------------
__global__ void quant_w8_kernel(const float* __restrict__ w) {
    const int b    = blockIdx.x;
    const int row  = blockIdx.y;
    const int lane = threadIdx.x;
    const float* src = w + (size_t)row * K_TOTAL + b * 64;

    float a0 = __ldg(src + lane);
    float a1 = __ldg(src + 32 + lane);
    float mx = fmaxf(fabsf(a0), fabsf(a1));
#pragma unroll
    for (int o = 16; o > 0; o >>= 1)
        mx = fmaxf(mx, __shfl_xor_sync(0xFFFFFFFFu, mx, o));
    int e = block_exp(mx);
    float scale = __int_as_float((e + 121) << 23);
    float inv   = __int_as_float((133 - e) << 23);
    int8_t* dst = g_wq8 + (size_t)row * K_TOTAL + b * 64;
    dst[lane]      = (int8_t)qint(a0, inv);
    dst[32 + lane] = (int8_t)qint(a1, inv);
    if (lane == 0) g_sw[b * C_OUT + row] = scale;
}

// ---------------------------------------------------------------------------
// Kernel 2: quantize im2col(A). grid (784, 9), 256 threads.
// Each thread owns one FULL 64-block of one row: thread-local max, no syncs.
// ---------------------------------------------------------------------------
template <int S>
__device__ __forceinline__ void gather64(const float* __restrict__ pix,
                                         uint32_t vmask, float* v, float& mx) {
#pragma unroll
    for (int e = 0; e < 64; ++e) {
        const int u   = S + e;
        const int ci  = u / 9;
        const int tap = u % 9;
        const int off = ci * IMG_PIX + (tap / 3) * HWDIM + (tap % 3);
        float val = ((vmask >> tap) & 1u) ? __ldg(pix + off) : 0.0f;
        v[e] = val;
        mx = fmaxf(mx, fabsf(val));
    }
}

__global__ void quant_a8_kernel(const float* __restrict__ inp) {
    const int tid = threadIdx.x;
    const int r   = tid & 127;
    const int h   = tid >> 7;              // which block of the pair
    const int y   = blockIdx.y;            // 0..8
    const int b   = 2 * y + h;             // 64-block index 0..17
    const int m   = blockIdx.x * 128 + r;
    const int c0  = (b * 64) / 9;

    const int ni = m / IMG_PIX;
    const int p  = m - ni * IMG_PIX;
    const int ho = p / HWDIM;
    const int wo = p - ho * HWDIM;
    const float* pix = inp + ((size_t)ni * C_IN + c0) * IMG_PIX
                       + ho * HWDIM + wo - 57;

    uint32_t vmask = 0;
#pragma unroll
    for (int kh = 0; kh < 3; ++kh)
#pragma unroll
        for (int kw = 0; kw < 3; ++kw) {
            int hh = ho + kh - 1, ww = wo + kw - 1;
            if ((unsigned)hh < (unsigned)HWDIM && (unsigned)ww < (unsigned)HWDIM)
                vmask |= 1u << (kh * 3 + kw);
        }

    float v[64];
    float mx = 0.0f;
    // t0 = (2y+h) % 9, dispatched at compile time per (y, h)
    switch (y) {
        case 0: if (h) gather64<1>(pix, vmask, v, mx); else gather64<0>(pix, vmask, v, mx); break;
        case 1: if (h) gather64<3>(pix, vmask, v, mx); else gather64<2>(pix, vmask, v, mx); break;
        case 2: if (h) gather64<5>(pix, vmask, v, mx); else gather64<4>(pix, vmask, v, mx); break;
        case 3: if (h) gather64<7>(pix, vmask, v, mx); else gather64<6>(pix, vmask, v, mx); break;
        case 4: if (h) gather64<0>(pix, vmask, v, mx); else gather64<8>(pix, vmask, v, mx); break;
        case 5: if (h) gather64<2>(pix, vmask, v, mx); else gather64<1>(pix, vmask, v, mx); break;
        case 6: if (h) gather64<4>(pix, vmask, v, mx); else gather64<3>(pix, vmask, v, mx); break;
        case 7: if (h) gather64<6>(pix, vmask, v, mx); else gather64<5>(pix, vmask, v, mx); break;
        default:if (h) gather64<8>(pix, vmask, v, mx); else gather64<7>(pix, vmask, v, mx); break;
    }

    int e = block_exp(mx);
    float scale = __int_as_float((e + 121) << 23);
    float inv   = __int_as_float((133 - e) << 23);

    uint32_t pk[16];
#pragma unroll
    for (int i = 0; i < 16; ++i)
        pk[i] = pack4(qint(v[4*i], inv),   qint(v[4*i+1], inv),
                      qint(v[4*i+2], inv), qint(v[4*i+3], inv));
    uint4* dst = reinterpret_cast<uint4*>(g_qa8 + (size_t)m * K_TOTAL + b * 64);
#pragma unroll
    for (int i = 0; i < 4; ++i)
        dst[i] = make_uint4(pk[4*i], pk[4*i+1], pk[4*i+2], pk[4*i+3]);
    g_sa[(size_t)b * M_TOTAL + m] = scale;
}

// ---------------------------------------------------------------------------
// Kernel 3: s8 GEMM. Tile 128x128, 256 threads (8 warps 4x2), warp 32x64.
// CHUNK_K=128 per stage; 9 iters; 3-stage cp.async ring, ONE sync per iter.
// Scales held in SMEM as u8 exponent bytes. 2 CTAs/SM.
// ---------------------------------------------------------------------------
#define A_SZ      16384
#define B_SZ      16384
#define STAGE     (A_SZ + B_SZ)         // 32768
#define NSTAGE    3
#define SCALE_OFF (NSTAGE * STAGE)      // 98304
#define SA_BYTES  (NBLK * 128)          // 2304
#define K3_SMEM   (SCALE_OFF + 2 * SA_BYTES)   // 102912
#define C_STRIDE  132

__global__ __launch_bounds__(256, 2)
void gemm8_kernel(const float* __restrict__ bias, float* __restrict__ out) {
    extern __shared__ __align__(16) char smem[];
    const uint32_t smem_u = cvta_smem(smem);
    uint8_t* sSA8 = reinterpret_cast<uint8_t*>(smem + SCALE_OFF);
    uint8_t* sSW8 = sSA8 + SA_BYTES;

    const int tid  = threadIdx.x;
    const int wid  = tid >> 5;
    const int lane = tid & 31;
    const int warp_m = wid & 3;
    const int warp_n = wid >> 2;
    const int ntile  = blockIdx.x;           // 0..1
    const int m_base = blockIdx.y * 128;

    // ---- preload scales as exponent bytes (exact: scales are pow2) ----
    for (int i = tid; i < SA_BYTES; i += 256)
        sSA8[i] = (uint8_t)(__float_as_uint(
            g_sa[(size_t)(i >> 7) * M_TOTAL + m_base + (i & 127)]) >> 23);
    for (int i = tid; i < SA_BYTES; i += 256)
        sSW8[i] = (uint8_t)(__float_as_uint(
            g_sw[(i >> 7) * C_OUT + ntile * 128 + (i & 127)]) >> 23);

    // ---- cp.async identities ----
    const int lr = tid >> 1;
    const int jh = (tid & 1) * 4;
    const uint32_t lkey = (uint32_t)(lr & 7);
    const int8_t* a_src = g_qa8 + (size_t)(m_base + lr) * K_TOTAL;
    const int8_t* b_src = g_wq8 + (size_t)(ntile * 128 + lr) * K_TOTAL;

    auto load_stage = [&](int kc, int s) {
        const uint32_t st = smem_u + s * STAGE;
        const int ko = kc * 128;
#pragma unroll
        for (int i = 0; i < 4; ++i) {
            uint32_t u = (uint32_t)(jh + i);
            uint32_t sw = ((u ^ lkey) << 4) + (uint32_t)(lr * 128);
            cp_async16(st + sw, a_src + ko + u * 16);
            cp_async16(st + A_SZ + sw, b_src + ko + u * 16);
        }
        cp_commit();
    };

    // ---- ldsm identities ----
    const uint32_t keyA = (uint32_t)(lane & 7);
    const uint32_t hiA  = (uint32_t)(lane >> 4);
    const uint32_t baseA = (uint32_t)((warp_m * 32 + (lane & 7)
                                       + ((lane >> 3) & 1) * 8) * 128);
    const uint32_t hiB  = (uint32_t)((lane >> 3) & 1);
    const uint32_t baseB = (uint32_t)(A_SZ + (warp_n * 64 + (lane & 7)
                                              + (lane >> 4) * 8) * 128);
    const int rs0 = warp_m * 32 + (lane >> 2);
    const int cs0 = warp_n * 64 + 2 * (lane & 3);

    float acc[16][4];
#pragma unroll
    for (int i = 0; i < 16; ++i)
#pragma unroll
        for (int j = 0; j < 4; ++j) acc[i][j] = 0.0f;

    load_stage(0, 0);
    load_stage(1, 1);

    int s = 0;
    for (int kc = 0; kc < 9; ++kc) {
        cp_wait<1>();
        __syncthreads();               // stage s ready for ALL warps; also
                                       // guarantees stage (s+2)%3 fully consumed
        const uint32_t sb = smem_u + s * STAGE;

#pragma unroll
        for (int blk = 0; blk < 2; ++blk) {
            const int gb = kc * 2 + blk;
            const float sa0 = __uint_as_float((uint32_t)sSA8[gb * 128 + rs0] << 23);
            const float sa1 = __uint_as_float((uint32_t)sSA8[gb * 128 + rs0 + 8] << 23);
            const float sa2 = __uint_as_float((uint32_t)sSA8[gb * 128 + rs0 + 16] << 23);
            const float sa3 = __uint_as_float((uint32_t)sSA8[gb * 128 + rs0 + 24] << 23);

            uint32_t a[2][2][4];
#pragma unroll
            for (int mt = 0; mt < 2; ++mt)
#pragma unroll
                for (int ks = 0; ks < 2; ++ks)
                    ldsm_x4(a[mt][ks], sb + baseA + mt * 2048
                            + ((((uint32_t)(blk * 4 + ks * 2) + hiA) ^ keyA) << 4));

#pragma unroll
            for (int ntp = 0; ntp < 4; ++ntp) {
                uint32_t b0[4], b1[4];
                ldsm_x4(b0, sb + baseB + ntp * 2048
                        + ((((uint32_t)(blk * 4) + hiB) ^ keyA) << 4));
                ldsm_x4(b1, sb + baseB + ntp * 2048
                        + ((((uint32_t)(blk * 4 + 2) + hiB) ^ keyA) << 4));
                const float sw0 = __uint_as_float(
                    (uint32_t)sSW8[gb * 128 + cs0 + ntp * 16] << 23);
                const float sw1 = __uint_as_float(
                    (uint32_t)sSW8[gb * 128 + cs0 + ntp * 16 + 1] << 23);
                const float sw2 = __uint_as_float(
                    (uint32_t)sSW8[gb * 128 + cs0 + ntp * 16 + 8] << 23);
                const float sw3 = __uint_as_float(
                    (uint32_t)sSW8[gb * 128 + cs0 + ntp * 16 + 9] << 23);
#pragma unroll
                for (int mt = 0; mt < 2; ++mt) {
                    const float ra = (mt == 0) ? sa0 : sa2;
                    const float rb = (mt == 0) ? sa1 : sa3;
#pragma unroll
                    for (int nf = 0; nf < 2; ++nf) {
                        int t[4];
                        imma_init(t, a[mt][0], b0[nf * 2], b0[nf * 2 + 1]);
                        imma_acc (t, a[mt][1], b1[nf * 2], b1[nf * 2 + 1]);
                        const float ca = nf ? sw2 : sw0;
                        const float cb = nf ? sw3 : sw1;
                        float* A_ = acc[mt * 8 + ntp * 2 + nf];
                        A_[0] += (ra * ca) * __int2float_rn(t[0]);
                        A_[1] += (ra * cb) * __int2float_rn(t[1]);
                        A_[2] += (rb * ca) * __int2float_rn(t[2]);
                        A_[3] += (rb * cb) * __int2float_rn(t[3]);
                    }
                }
            }
        }

        // load stage kc+2 into the ring slot freed at kc-1 (safe: the barrier
        // above proved every warp finished compute(kc-1))
        if (kc + 2 < 9) load_stage(kc + 2, (s + 2 >= NSTAGE) ? s - 1 : s + 2);
        else cp_commit();
        if (++s == NSTAGE) s = 0;
    }

    // ---- epilogue: transpose via SMEM, coalesced NCHW stores + bias ----
    __syncthreads();
    float* sC = reinterpret_cast<float*>(smem);
#pragma unroll
    for (int mt = 0; mt < 2; ++mt)
#pragma unroll
        for (int nt = 0; nt < 8; ++nt) {
            int rr = warp_m * 32 + mt * 16 + (lane >> 2);
            int cc = warp_n * 64 + nt * 8 + 2 * (lane & 3);
            float* f = acc[mt * 8 + nt];
            sC[cc * C_STRIDE + rr]           = f[0];
            sC[(cc + 1) * C_STRIDE + rr]     = f[1];
            sC[cc * C_STRIDE + rr + 8]       = f[2];
            sC[(cc + 1) * C_STRIDE + rr + 8] = f[3];
        }
    __syncthreads();

#pragma unroll
    for (int j = 0; j < 4; ++j) {
        int rr = j * 32 + lane;
        int mm = m_base + rr;
        int ni2 = mm / IMG_PIX;
        int pp  = mm - ni2 * IMG_PIX;
        float* ob = out + (size_t)ni2 * (C_OUT * IMG_PIX) + pp;
#pragma unroll 4
        for (int i = 0; i < 16; ++i) {
            int cl = wid * 16 + i;
            int co = ntile * 128 + cl;
            ob[(size_t)co * IMG_PIX] = sC[cl * C_STRIDE + rr] + __ldg(bias + co);
        }
    }
}

// ---------------------------------------------------------------------------
extern "C" void kernel_launch(void* const* d_in, const int* in_sizes, int n_in,
                              void* d_out, int out_size) {
    (void)in_sizes; (void)n_in; (void)out_size;
    const float* inp  = (const float*)d_in[0];
    const float* w    = (const float*)d_in[1];
    const float* bias = (const float*)d_in[2];
    float* out = (float*)d_out;

    cudaFuncSetAttribute(gemm8_kernel,
                         cudaFuncAttributeMaxDynamicSharedMemorySize, K3_SMEM);

    quant_w8_kernel<<<dim3(NBLK, C_OUT, 1), 32>>>(w);
    quant_a8_kernel<<<dim3(GRID_M, 9, 1), 256>>>(inp);
    gemm8_kernel<<<dim3(2, GRID_M, 1), 256, K3_SMEM>>>(bias, out);
}

// round 11
// speedup vs baseline: 1.0580x; 1.0154x over previous
#include <cuda_runtime.h>
#include <cuda_bf16.h>
#include <stdint.h>

// ============================================================================
// BFP8 quantized 3x3 conv (stride 1, pad 1) == GEMM M=100352, N=256, K=1152
// Round 11: int8 IMMA path; quantization via magic-number FFMA:
//   rint(x*inv) == low-byte of float_bits(fma(x, inv, 1.5*2^23)); one FMNMX
//   clamps the q=+128 edge. Cuts quant_a per-value ops ~30%.
//   GEMM identical to Round 10 (3-stage ring, one sync/chunk, u8-exp scales).
// ============================================================================

#define C_IN      128
#define C_OUT     256
#define HWDIM     56
#define IMG_PIX   3136
#define K_TOTAL   1152
#define M_TOTAL   100352
#define GRID_M    784
#define NBLK      18

#define QMAGIC    12582912.0f          // 1.5 * 2^23
#define QCLAMP    12583039.0f          // QMAGIC + 127

__device__ __align__(16) int8_t g_wq8[C_OUT * K_TOTAL];
__device__ float   g_sw[NBLK * C_OUT];                    // [b][n]
__device__ __align__(16) int8_t g_qa8[(size_t)M_TOTAL * K_TOTAL];   // 110 MB
__device__ float   g_sa[(size_t)NBLK * M_TOTAL];          // [b][m]

// ---------------------------------------------------------------------------
__device__ __forceinline__ uint32_t cvta_smem(const void* p) {
    uint32_t a;
    asm("{ .reg .u64 t; cvta.to.shared.u64 t, %1; cvt.u32.u64 %0, t; }"
        : "=r"(a) : "l"(p));
    return a;
}
__device__ __forceinline__ void ldsm_x4(uint32_t* d, uint32_t addr) {
    asm volatile("ldmatrix.sync.aligned.m8n8.x4.shared.b16 {%0,%1,%2,%3}, [%4];"
                 : "=r"(d[0]), "=r"(d[1]), "=r"(d[2]), "=r"(d[3]) : "r"(addr));
}
__device__ __forceinline__ void imma_init(int* d, const uint32_t* a,
                                          uint32_t b0, uint32_t b1) {
    asm volatile(
        "mma.sync.aligned.m16n8k32.row.col.s32.s8.s8.s32 "
        "{%0,%1,%2,%3}, {%4,%5,%6,%7}, {%8,%9}, {%10,%10,%10,%10};"
        : "=r"(d[0]), "=r"(d[1]), "=r"(d[2]), "=r"(d[3])
        : "r"(a[0]), "r"(a[1]), "r"(a[2]), "r"(a[3]),
          "r"(b0), "r"(b1), "r"(0));
}
__device__ __forceinline__ void imma_acc(int* d, const uint32_t* a,
                                         uint32_t b0, uint32_t b1) {
    asm volatile(
        "mma.sync.aligned.m16n8k32.row.col.s32.s8.s8.s32 "
        "{%0,%1,%2,%3}, {%4,%5,%6,%7}, {%8,%9}, {%0,%1,%2,%3};"
        : "+r"(d[0]), "+r"(d[1]), "+r"(d[2]), "+r"(d[3])
        : "r"(a[0]), "r"(a[1]), "r"(a[2]), "r"(a[3]), "r"(b0), "r"(b1));
}
__device__ __forceinline__ void cp_async16(uint32_t dst, const void* src) {
    asm volatile("cp.async.cg.shared.global [%0], [%1], 16;" :: "r"(dst), "l"(src));
}
__device__ __forceinline__ void cp_commit() {
    asm volatile("cp.async.commit_group;");
}
template <int N>
__device__ __forceinline__ void cp_wait() {
    asm volatile("cp.async.wait_group %0;" :: "n"(N));
}

__device__ __forceinline__ int block_exp(float mx) {
    mx = fmaxf(mx, 1e-38f);
    return ((__float_as_int(mx) >> 23) & 255) - 127;
}
// magic quantize: returns float whose low byte is the s8 mantissa
__device__ __forceinline__ uint32_t qmagic(float x, float inv) {
    return __float_as_uint(fminf(fmaf(x, inv, QMAGIC), QCLAMP));
}
__device__ __forceinline__ uint32_t qpack4(float v0, float v1, float v2,
                                           float v3, float inv) {
    uint32_t u0 = qmagic(v0, inv), u1 = qmagic(v1, inv);
    uint32_t u2 = qmagic(v2, inv), u3 = qmagic(v3, inv);
    return __byte_perm(__byte_perm(u0, u1, 0x0040),
                       __byte_perm(u2, u3, 0x0040), 0x5410);
}

// ---------------------------------------------------------------------------
// Kernel 1: quantize weight. One warp per (row, 64-block). grid (18, 256).
// ---------------------------------------------------------------------------
__global__ void quant_w8_kernel(const float* __restrict__ w) {
    const int b    = blockIdx.x;
    const int row  = blockIdx.y;
    const int lane = threadIdx.x;
    const float* src = w + (size_t)row * K_TOTAL + b * 64;

    float a0 = __ldg(src + lane);
    float a1 = __ldg(src + 32 + lane);
    float mx = fmaxf(fabsf(a0), fabsf(a1));
#pragma unroll
    for (int o = 16; o > 0; o >>= 1)
        mx = fmaxf(mx, __shfl_xor_sync(0xFFFFFFFFu, mx, o));
    int e = block_exp(mx);
    float inv = __int_as_float((133 - e) << 23);
    int8_t* dst = g_wq8 + (size_t)row * K_TOTAL + b * 64;
    dst[lane]      = (int8_t)(qmagic(a0, inv) & 0xFF);
    dst[32 + lane] = (int8_t)(qmagic(a1, inv) & 0xFF);
    if (lane == 0) g_sw[b * C_OUT + row] = __int_as_float((e + 121) << 23);
}

// ---------------------------------------------------------------------------
// Kernel 2: quantize im2col(A). grid (784, 9), 256 threads.
// One full 64-block per thread; 4-way max tree; magic-FFMA quantize.
// ---------------------------------------------------------------------------
template <int S>
__device__ __forceinline__ void gather64(const float* __restrict__ pix,
                                         uint32_t vmask, float* v, float* mx4) {
#pragma unroll
    for (int e = 0; e < 64; ++e) {
        const int u   = S + e;
        const int ci  = u / 9;
        const int tap = u % 9;
        const int off = ci * IMG_PIX + (tap / 3) * HWDIM + (tap % 3);
        float val = ((vmask >> tap) & 1u) ? __ldg(pix + off) : 0.0f;
        v[e] = val;
        mx4[e & 3] = fmaxf(mx4[e & 3], fabsf(val));
    }
}

__global__ void quant_a8_kernel(const float* __restrict__ inp) {
    const int tid = threadIdx.x;
    const int r   = tid & 127;
    const int h   = tid >> 7;
    const int y   = blockIdx.y;            // 0..8
    const int b   = 2 * y + h;             // 64-block index 0..17
    const int m   = blockIdx.x * 128 + r;
    const int c0  = (b * 64) / 9;

    const int ni = m / IMG_PIX;
    const int p  = m - ni * IMG_PIX;
    const int ho = p / HWDIM;
    const int wo = p - ho * HWDIM;
    const float* pix = inp + ((size_t)ni * C_IN + c0) * IMG_PIX
                       + ho * HWDIM + wo - 57;

    uint32_t vmask = 0;
#pragma unroll
    for (int kh = 0; kh < 3; ++kh)
#pragma unroll
        for (int kw = 0; kw < 3; ++kw) {
            int hh = ho + kh - 1, ww = wo + kw - 1;
            if ((unsigned)hh < (unsigned)HWDIM && (unsigned)ww < (unsigned)HWDIM)
                vmask |= 1u << (kh * 3 + kw);
        }

    float v[64];
    float mx4[4] = {0.0f, 0.0f, 0.0f, 0.0f};
    switch (y) {
        case 0: if (h) gather64<1>(pix, vmask, v, mx4); else gather64<0>(pix, vmask, v, mx4); break;
        case 1: if (h) gather64<3>(pix, vmask, v, mx4); else gather64<2>(pix, vmask, v, mx4); break;
        case 2: if (h) gather64<5>(pix, vmask, v, mx4); else gather64<4>(pix, vmask, v, mx4); break;
        case 3: if (h) gather64<7>(pix, vmask, v, mx4); else gather64<6>(pix, vmask, v, mx4); break;
        case 4: if (h) gather64<0>(pix, vmask, v, mx4); else gather64<8>(pix, vmask, v, mx4); break;
        case 5: if (h) gather64<2>(pix, vmask, v, mx4); else gather64<1>(pix, vmask, v, mx4); break;
        case 6: if (h) gather64<4>(pix, vmask, v, mx4); else gather64<3>(pix, vmask, v, mx4); break;
        case 7: if (h) gather64<6>(pix, vmask, v, mx4); else gather64<5>(pix, vmask, v, mx4); break;
        default:if (h) gather64<8>(pix, vmask, v, mx4); else gather64<7>(pix, vmask, v, mx4); break;
    }
    float mx = fmaxf(fmaxf(mx4[0], mx4[1]), fmaxf(mx4[2], mx4[3]));

    int e = block_exp(mx);
    float inv = __int_as_float((133 - e) << 23);

    uint32_t pk[16];
#pragma unroll
    for (int i = 0; i < 16; ++i)
        pk[i] = qpack4(v[4*i], v[4*i+1], v[4*i+2], v[4*i+3], inv);

    uint4* dst = reinterpret_cast<uint4*>(g_qa8 + (size_t)m * K_TOTAL + b * 64);
#pragma unroll
    for (int i = 0; i < 4; ++i)
        dst[i] = make_uint4(pk[4*i], pk[4*i+1], pk[4*i+2], pk[4*i+3]);
    g_sa[(size_t)b * M_TOTAL + m] = __int_as_float((e + 121) << 23);
}

// ---------------------------------------------------------------------------
// Kernel 3: s8 GEMM (identical to Round 10). Tile 128x128, 256 thr, 3-stage
// ring with one sync per chunk, u8-exponent scales in SMEM, 2 CTAs/SM.
// ---------------------------------------------------------------------------
#define A_SZ      16384
#define B_SZ      16384
#define STAGE     (A_SZ + B_SZ)
#define NSTAGE    3
#define SCALE_OFF (NSTAGE * STAGE)
#define SA_BYTES  (NBLK * 128)
#define K3_SMEM   (SCALE_OFF + 2 * SA_BYTES)
#define C_STRIDE  132

__global__ __launch_bounds__(256, 2)
void gemm8_kernel(const float* __restrict__ bias, float* __restrict__ out) {
    extern __shared__ __align__(16) char smem[];
    const uint32_t smem_u = cvta_smem(smem);
    uint8_t* sSA8 = reinterpret_cast<uint8_t*>(smem + SCALE_OFF);
    uint8_t* sSW8 = sSA8 + SA_BYTES;

    const int tid  = threadIdx.x;
    const int wid  = tid >> 5;
    const int lane = tid & 31;
    const int warp_m = wid & 3;
    const int warp_n = wid >> 2;
    const int ntile  = blockIdx.x;
    const int m_base = blockIdx.y * 128;

    for (int i = tid; i < SA_BYTES; i += 256)
        sSA8[i] = (uint8_t)(__float_as_uint(
            g_sa[(size_t)(i >> 7) * M_TOTAL + m_base + (i & 127)]) >> 23);
    for (int i = tid; i < SA_BYTES; i += 256)
        sSW8[i] = (uint8_t)(__float_as_uint(
            g_sw[(i >> 7) * C_OUT + ntile * 128 + (i & 127)]) >> 23);

    const int lr = tid >> 1;
    const int jh = (tid & 1) * 4;
    const uint32_t lkey = (uint32_t)(lr & 7);
    const int8_t* a_src = g_qa8 + (size_t)(m_base + lr) * K_TOTAL;
    const int8_t* b_src = g_wq8 + (size_t)(ntile * 128 + lr) * K_TOTAL;

    auto load_stage = [&](int kc, int s) {
        const uint32_t st = smem_u + s * STAGE;
        const int ko = kc * 128;
#pragma unroll
        for (int i = 0; i < 4; ++i) {
            uint32_t u = (uint32_t)(jh + i);
            uint32_t sw = ((u ^ lkey) << 4) + (uint32_t)(lr * 128);
            cp_async16(st + sw, a_src + ko + u * 16);
            cp_async16(st + A_SZ + sw, b_src + ko + u * 16);
        }
        cp_commit();
    };

    const uint32_t keyA = (uint32_t)(lane & 7);
    const uint32_t hiA  = (uint32_t)(lane >> 4);
    const uint32_t baseA = (uint32_t)((warp_m * 32 + (lane & 7)
                                       + ((lane >> 3) & 1) * 8) * 128);
    const uint32_t hiB  = (uint32_t)((lane >> 3) & 1);
    const uint32_t baseB = (uint32_t)(A_SZ + (warp_n * 64 + (lane & 7)
                                              + (lane >> 4) * 8) * 128);
    const int rs0 = warp_m * 32 + (lane >> 2);
    const int cs0 = warp_n * 64 + 2 * (lane & 3);

    float acc[16][4];
#pragma unroll
    for (int i = 0; i < 16; ++i)
#pragma unroll
        for (int j = 0; j < 4; ++j) acc[i][j] = 0.0f;

    load_stage(0, 0);
    load_stage(1, 1);

    int s = 0;
    for (int kc = 0; kc < 9; ++kc) {
        cp_wait<1>();
        __syncthreads();
        const uint32_t sb = smem_u + s * STAGE;

#pragma unroll
        for (int blk = 0; blk < 2; ++blk) {
            const int gb = kc * 2 + blk;
            const float sa0 = __uint_as_float((uint32_t)sSA8[gb * 128 + rs0] << 23);
            const float sa1 = __uint_as_float((uint32_t)sSA8[gb * 128 + rs0 + 8] << 23);
            const float sa2 = __uint_as_float((uint32_t)sSA8[gb * 128 + rs0 + 16] << 23);
            const float sa3 = __uint_as_float((uint32_t)sSA8[gb * 128 + rs0 + 24] << 23);

            uint32_t a[2][2][4];
#pragma unroll
            for (int mt = 0; mt < 2; ++mt)
#pragma unroll
                for (int ks = 0; ks < 2; ++ks)
                    ldsm_x4(a[mt][ks], sb + baseA + mt * 2048
                            + ((((uint32_t)(blk * 4 + ks * 2) + hiA) ^ keyA) << 4));

#pragma unroll
            for (int ntp = 0; ntp < 4; ++ntp) {
                uint32_t b0[4], b1[4];
                ldsm_x4(b0, sb + baseB + ntp * 2048
                        + ((((uint32_t)(blk * 4) + hiB) ^ keyA) << 4));
                ldsm_x4(b1, sb + baseB + ntp * 2048
                        + ((((uint32_t)(blk * 4 + 2) + hiB) ^ keyA) << 4));
                const float sw0 = __uint_as_float(
                    (uint32_t)sSW8[gb * 128 + cs0 + ntp * 16] << 23);
                const float sw1 = __uint_as_float(
                    (uint32_t)sSW8[gb * 128 + cs0 + ntp * 16 + 1] << 23);
                const float sw2 = __uint_as_float(
                    (uint32_t)sSW8[gb * 128 + cs0 + ntp * 16 + 8] << 23);
                const float sw3 = __uint_as_float(
                    (uint32_t)sSW8[gb * 128 + cs0 + ntp * 16 + 9] << 23);
#pragma unroll
                for (int mt = 0; mt < 2; ++mt) {
                    const float ra = (mt == 0) ? sa0 : sa2;
                    const float rb = (mt == 0) ? sa1 : sa3;
#pragma unroll
                    for (int nf = 0; nf < 2; ++nf) {
                        int t[4];
                        imma_init(t, a[mt][0], b0[nf * 2], b0[nf * 2 + 1]);
                        imma_acc (t, a[mt][1], b1[nf * 2], b1[nf * 2 + 1]);
                        const float ca = nf ? sw2 : sw0;
                        const float cb = nf ? sw3 : sw1;
                        float* A_ = acc[mt * 8 + ntp * 2 + nf];
                        A_[0] += (ra * ca) * __int2float_rn(t[0]);
                        A_[1] += (ra * cb) * __int2float_rn(t[1]);
                        A_[2] += (rb * ca) * __int2float_rn(t[2]);
                        A_[3] += (rb * cb) * __int2float_rn(t[3]);
                    }
                }
            }
        }

        if (kc + 2 < 9) load_stage(kc + 2, (s + 2 >= NSTAGE) ? s - 1 : s + 2);
        else cp_commit();
        if (++s == NSTAGE) s = 0;
    }

    __syncthreads();
    float* sC = reinterpret_cast<float*>(smem);
#pragma unroll
    for (int mt = 0; mt < 2; ++mt)
#pragma unroll
        for (int nt = 0; nt < 8; ++nt) {
            int rr = warp_m * 32 + mt * 16 + (lane >> 2);
            int cc = warp_n * 64 + nt * 8 + 2 * (lane & 3);
            float* f = acc[mt * 8 + nt];
            sC[cc * C_STRIDE + rr]           = f[0];
            sC[(cc + 1) * C_STRIDE + rr]     = f[1];
            sC[cc * C_STRIDE + rr + 8]       = f[2];
            sC[(cc + 1) * C_STRIDE + rr + 8] = f[3];
        }
    __syncthreads();

#pragma unroll
    for (int j = 0; j < 4; ++j) {
        int rr = j * 32 + lane;
        int mm = m_base + rr;
        int ni2 = mm / IMG_PIX;
        int pp  = mm - ni2 * IMG_PIX;
        float* ob = out + (size_t)ni2 * (C_OUT * IMG_PIX) + pp;
#pragma unroll 4
        for (int i = 0; i < 16; ++i) {
            int cl = wid * 16 + i;
            int co = ntile * 128 + cl;
            ob[(size_t)co * IMG_PIX] = sC[cl * C_STRIDE + rr] + __ldg(bias + co);
        }
    }
}

// ---------------------------------------------------------------------------
extern "C" void kernel_launch(void* const* d_in, const int* in_sizes, int n_in,
                              void* d_out, int out_size) {
    (void)in_sizes; (void)n_in; (void)out_size;
    const float* inp  = (const float*)d_in[0];
    const float* w    = (const float*)d_in[1];
    const float* bias = (const float*)d_in[2];
    float* out = (float*)d_out;

    cudaFuncSetAttribute(gemm8_kernel,
                         cudaFuncAttributeMaxDynamicSharedMemorySize, K3_SMEM);

    quant_w8_kernel<<<dim3(NBLK, C_OUT, 1), 32>>>(w);
    quant_a8_kernel<<<dim3(GRID_M, 9, 1), 256>>>(inp);
    gemm8_kernel<<<dim3(2, GRID_M, 1), 256, K3_SMEM>>>(bias, out);
}